// round 11
// baseline (speedup 1.0000x reference)
#include <cuda_runtime.h>
#include <cuda_bf16.h>
#include <cstdint>

#define ROWSTRIDE 5248
#define NTILES2   2624          // 41 s * 32 mtiles * 2 nhalves
#define GRIDSZ    304
#define NTHREADS  384
#define SMEM_BYTES 49152

#define STAGE  24576u
#define SX_LO  8192u
#define SW_HI  16384u
#define SW_LO  20480u

static __device__ __forceinline__ uint32_t smem_u32(const void* p) {
    uint32_t a;
    asm("{ .reg .u64 t; cvta.to.shared.u64 t, %1; cvt.u32.u64 %0, t; }"
        : "=r"(a) : "l"(p));
    return a;
}
static __device__ __forceinline__ void ldsm4(uint32_t* r, uint32_t a) {
    asm volatile("ldmatrix.sync.aligned.m8n8.x4.shared.b16 {%0,%1,%2,%3}, [%4];"
                 : "=r"(r[0]), "=r"(r[1]), "=r"(r[2]), "=r"(r[3]) : "r"(a));
}
static __device__ __forceinline__ void ldsm4t(uint32_t* r, uint32_t a) {
    asm volatile("ldmatrix.sync.aligned.m8n8.x4.trans.shared.b16 {%0,%1,%2,%3}, [%4];"
                 : "=r"(r[0]), "=r"(r[1]), "=r"(r[2]), "=r"(r[3]) : "r"(a));
}
static __device__ __forceinline__ void mma_bf16(float* c, const uint32_t* a, const uint32_t* b) {
    asm volatile("mma.sync.aligned.m16n8k16.row.col.f32.bf16.bf16.f32 "
                 "{%0,%1,%2,%3}, {%4,%5,%6,%7}, {%8,%9}, {%0,%1,%2,%3};"
                 : "+f"(c[0]), "+f"(c[1]), "+f"(c[2]), "+f"(c[3])
                 : "r"(a[0]), "r"(a[1]), "r"(a[2]), "r"(a[3]), "r"(b[0]), "r"(b[1]));
}
static __device__ __forceinline__ uint32_t hi2(float a, float b, float& ra, float& rb) {
    __nv_bfloat16 ha = __float2bfloat16(a), hb = __float2bfloat16(b);
    ra = a - __bfloat162float(ha);
    rb = b - __bfloat162float(hb);
    return (uint32_t)__bfloat16_as_ushort(ha) | ((uint32_t)__bfloat16_as_ushort(hb) << 16);
}
static __device__ __forceinline__ uint32_t lo2(float a, float b) {
    return (uint32_t)__bfloat16_as_ushort(__float2bfloat16(a)) |
           ((uint32_t)__bfloat16_as_ushort(__float2bfloat16(b)) << 16);
}

__global__ void __launch_bounds__(NTHREADS, 2)
poslin_kernel(const float* __restrict__ x, const float* __restrict__ W,
              const float* __restrict__ bias, float* __restrict__ out)
{
    extern __shared__ __align__(128) char smem[];
    const uint32_t sb = smem_u32(smem);
    const int tid  = threadIdx.x;
    const int lane = tid & 31;
    const int wid  = tid >> 5;                 // 0..11

    const int start = (int)(((long)blockIdx.x * NTILES2) / GRIDSZ);
    const int end   = (int)(((long)(blockIdx.x + 1) * NTILES2) / GRIDSZ);
    const int Ctot  = (end - start) * 12;      // 12 K32-chunks per tile

    if (wid >= 8) {
        // ============ PRODUCER (4 warps): LDG one chunk ahead of STS ========
        const int ptid = tid - 256;            // 0..127
        const int kq  = ptid & 7,  xr0 = ptid >> 3;   // x: k4 idx, row base 0..15
        const int wq  = ptid & 15, wk0 = ptid >> 4;   // W: f4-in-row, k base 0..7

        float4 xa[8], wa[4];
        int tL = start, cL = 0;

#define LDGC() do {                                                             \
    const int s_ = tL >> 6, r_ = tL & 63;                                       \
    const int bb_ = (r_ >> 1) << 7, nh_ = r_ & 1;                               \
    const int e_ = (s_ - 1) * 128 + cL * 32 + kq * 4;                           \
    const bool v_ = (e_ >= 0) && (e_ < ROWSTRIDE);                              \
    const float* Wc_ = W + (size_t)s_ * 49152 + (size_t)(cL * 32) * 128 + nh_ * 64; \
    _Pragma("unroll")                                                           \
    for (int it = 0; it < 8; ++it)                                              \
        xa[it] = v_ ? *(const float4*)(x + (size_t)(bb_ + xr0 + 16*it) * ROWSTRIDE + e_) \
                    : make_float4(0.f, 0.f, 0.f, 0.f);                          \
    _Pragma("unroll")                                                           \
    for (int it = 0; it < 4; ++it)                                              \
        wa[it] = *(const float4*)(Wc_ + (size_t)(wk0 + 8*it) * 128 + wq * 4);   \
} while (0)

#define STSC(bufv) do {                                                         \
    const uint32_t bo_ = (uint32_t)(bufv) * STAGE;                              \
    _Pragma("unroll")                                                           \
    for (int it = 0; it < 8; ++it) {                                            \
        const uint32_t row = (uint32_t)(xr0 + 16*it);                           \
        float r0_, r1_, r2_, r3_;                                               \
        uint32_t h0_ = hi2(xa[it].x, xa[it].y, r0_, r1_);                       \
        uint32_t h1_ = hi2(xa[it].z, xa[it].w, r2_, r3_);                       \
        uint32_t o_ = bo_ + (row >> 1) * 128u                                   \
                    + (((((row & 1u) << 2) + (uint32_t)(kq >> 1))               \
                        ^ ((row >> 1) & 7u)) << 4)                              \
                    + (uint32_t)((kq & 1) << 3);                                \
        *(uint2*)(smem + o_)         = make_uint2(h0_, h1_);                    \
        *(uint2*)(smem + o_ + SX_LO) = make_uint2(lo2(r0_, r1_), lo2(r2_, r3_));\
    }                                                                           \
    _Pragma("unroll")                                                           \
    for (int it = 0; it < 4; ++it) {                                            \
        const uint32_t kr = (uint32_t)(wk0 + 8*it);                             \
        float r0_, r1_, r2_, r3_;                                               \
        uint32_t h0_ = hi2(wa[it].x, wa[it].y, r0_, r1_);                       \
        uint32_t h1_ = hi2(wa[it].z, wa[it].w, r2_, r3_);                       \
        uint32_t o_ = bo_ + SW_HI + kr * 128u                                   \
                    + ((((uint32_t)(wq >> 1)) ^ (kr & 7u)) << 4)                \
                    + (uint32_t)((wq & 1) << 3);                                \
        *(uint2*)(smem + o_)                   = make_uint2(h0_, h1_);          \
        *(uint2*)(smem + o_ + (SW_LO - SW_HI)) = make_uint2(lo2(r0_, r1_), lo2(r2_, r3_)); \
    }                                                                           \
} while (0)

        LDGC();
        STSC(0);
        if (++cL == 12) { cL = 0; ++tL; }
        if (Ctot > 1) LDGC();

        for (int g = 0; g < Ctot; ++g) {
            __syncthreads();
            if (g + 1 < Ctot) {
                STSC((g + 1) & 1);
                if (++cL == 12) { cL = 0; ++tL; }
                if (g + 2 < Ctot) LDGC();
            }
        }
#undef LDGC
#undef STSC
    } else {
        // ================= CONSUMER (8 warps, 256 threads) =================
        const int m0 = (wid & 3) << 5;         // 0,32,64,96
        const int n0 = (wid >> 2) << 5;        // 0,32 (within 64-wide half)
        const int g8 = lane >> 2, tig = lane & 3;

        const uint32_t aRow = (uint32_t)(m0 + (lane & 15));
        const uint32_t aKC  = (uint32_t)(lane >> 4);         // 0/1
        const uint32_t l7   = (uint32_t)(lane & 7);
        const uint32_t bKr  = (uint32_t)(lane & 15);
        const uint32_t bNC  = (uint32_t)((n0 >> 3) + (lane >> 4));

        int t = start, c = 0;
        float acc[2][4][4];

        for (int g = 0; g < Ctot; ++g) {
            __syncthreads();
            if (c == 0) {
                _Pragma("unroll")
                for (int i = 0; i < 2; ++i)
                    _Pragma("unroll")
                    for (int j = 0; j < 4; ++j)
                        _Pragma("unroll")
                        for (int u = 0; u < 4; ++u) acc[i][j][u] = 0.f;
            }
            {
                const uint32_t Ab = sb + (uint32_t)(g & 1) * STAGE;
                _Pragma("unroll")
                for (int ks = 0; ks < 2; ++ks) {
                    uint32_t ah[2][4], al[2][4];
                    _Pragma("unroll")
                    for (int i = 0; i < 2; ++i) {
                        const uint32_t row = aRow + 16u * i;
                        const uint32_t cidx = ((uint32_t)(ks * 2)) + aKC;
                        uint32_t ad = Ab + (row >> 1) * 128u
                                    + (((((row & 1u) << 2) + cidx) ^ ((row >> 1) & 7u)) << 4);
                        ldsm4(ah[i], ad);
                        ldsm4(al[i], ad + SX_LO);
                    }
                    _Pragma("unroll")
                    for (int jj = 0; jj < 2; ++jj) {
                        uint32_t bd = Ab + SW_HI + (bKr + 16u * ks) * 128u
                                    + (((bNC + 2u * jj) ^ l7) << 4);
                        uint32_t bh_[4], bl_[4];
                        ldsm4t(bh_, bd);
                        ldsm4t(bl_, bd + (SW_LO - SW_HI));
                        _Pragma("unroll")
                        for (int i = 0; i < 2; ++i) {
                            mma_bf16(acc[i][2*jj],     ah[i], bh_);
                            mma_bf16(acc[i][2*jj + 1], ah[i], bh_ + 2);
                            mma_bf16(acc[i][2*jj],     al[i], bh_);
                            mma_bf16(acc[i][2*jj + 1], al[i], bh_ + 2);
                        }
                        _Pragma("unroll")
                        for (int i = 0; i < 2; ++i) {
                            mma_bf16(acc[i][2*jj],     ah[i], bl_);
                            mma_bf16(acc[i][2*jj + 1], ah[i], bl_ + 2);
                        }
                    }
                }
            }
            if (c == 11) {
                const int s = t >> 6, r_ = t & 63;
                const int bbase = (r_ >> 1) << 7, noff = (r_ & 1) << 6;
                const float* brow = bias + s * 128 + noff;
                _Pragma("unroll")
                for (int j = 0; j < 4; ++j) {
                    const int n = n0 + 8 * j + 2 * tig;
                    const float b0 = brow[n], b1 = brow[n + 1];
                    _Pragma("unroll")
                    for (int i = 0; i < 2; ++i) {
                        const size_t rb = (size_t)(bbase + m0 + 16 * i + g8) * ROWSTRIDE
                                        + (size_t)s * 128 + noff + n;
                        float2 v0, v1;
                        v0.x = fmaxf(acc[i][j][0] + b0, 0.f);
                        v0.y = fmaxf(acc[i][j][1] + b1, 0.f);
                        v1.x = fmaxf(acc[i][j][2] + b0, 0.f);
                        v1.y = fmaxf(acc[i][j][3] + b1, 0.f);
                        *(float2*)(out + rb)                 = v0;
                        *(float2*)(out + rb + 8 * ROWSTRIDE) = v1;
                    }
                }
            }
            if (++c == 12) { c = 0; ++t; }
        }
    }
}

extern "C" void kernel_launch(void* const* d_in, const int* in_sizes, int n_in,
                              void* d_out, int out_size) {
    const float* x = (const float*)d_in[0];
    const float* W = (const float*)d_in[1];
    const float* b = (const float*)d_in[2];
    float* out = (float*)d_out;
    cudaFuncSetAttribute(poslin_kernel,
                         cudaFuncAttributeMaxDynamicSharedMemorySize, SMEM_BYTES);
    poslin_kernel<<<GRIDSZ, NTHREADS, SMEM_BYTES>>>(x, W, b, out);
}

// round 12
// speedup vs baseline: 1.0308x; 1.0308x over previous
#include <cuda_runtime.h>
#include <cuda_bf16.h>
#include <cstdint>

#define ROWSTRIDE 5248
#define NTILES    1312
#define GRIDSZ    148
#define NTHREADS  640
#define SMEM_BYTES 131072

#define BUFSTR 65536u
#define O_XLO  16384u
#define O_WHI  32768u
// W lo lives at O_WHI + 16384 inside each buffer

// Pre-split W image: per s (41): 6 chunks x 32768 B (hi 16KB + lo 16KB), pre-swizzled
#define WPRE_PER_S 196608
__device__ __align__(16) unsigned char g_wpre[41 * WPRE_PER_S];

static __device__ __forceinline__ uint32_t smem_u32(const void* p) {
    uint32_t a;
    asm("{ .reg .u64 t; cvta.to.shared.u64 t, %1; cvt.u32.u64 %0, t; }"
        : "=r"(a) : "l"(p));
    return a;
}
static __device__ __forceinline__ void ldsm4(uint32_t* r, uint32_t a) {
    asm volatile("ldmatrix.sync.aligned.m8n8.x4.shared.b16 {%0,%1,%2,%3}, [%4];"
                 : "=r"(r[0]), "=r"(r[1]), "=r"(r[2]), "=r"(r[3]) : "r"(a));
}
static __device__ __forceinline__ void ldsm4t(uint32_t* r, uint32_t a) {
    asm volatile("ldmatrix.sync.aligned.m8n8.x4.trans.shared.b16 {%0,%1,%2,%3}, [%4];"
                 : "=r"(r[0]), "=r"(r[1]), "=r"(r[2]), "=r"(r[3]) : "r"(a));
}
static __device__ __forceinline__ void mma_bf16(float* c, const uint32_t* a, const uint32_t* b) {
    asm volatile("mma.sync.aligned.m16n8k16.row.col.f32.bf16.bf16.f32 "
                 "{%0,%1,%2,%3}, {%4,%5,%6,%7}, {%8,%9}, {%0,%1,%2,%3};"
                 : "+f"(c[0]), "+f"(c[1]), "+f"(c[2]), "+f"(c[3])
                 : "r"(a[0]), "r"(a[1]), "r"(a[2]), "r"(a[3]), "r"(b[0]), "r"(b[1]));
}
static __device__ __forceinline__ uint32_t hi2(float a, float b, float& ra, float& rb) {
    __nv_bfloat16 ha = __float2bfloat16(a), hb = __float2bfloat16(b);
    ra = a - __bfloat162float(ha);
    rb = b - __bfloat162float(hb);
    return (uint32_t)__bfloat16_as_ushort(ha) | ((uint32_t)__bfloat16_as_ushort(hb) << 16);
}
static __device__ __forceinline__ uint32_t lo2(float a, float b) {
    return (uint32_t)__bfloat16_as_ushort(__float2bfloat16(a)) |
           ((uint32_t)__bfloat16_as_ushort(__float2bfloat16(b)) << 16);
}
static __device__ __forceinline__ void cp16(uint32_t dst, const void* src) {
    asm volatile("cp.async.cg.shared.global [%0], [%1], 16;"
                 :: "r"(dst), "l"(src) : "memory");
}

// ---------------- precompute: W -> swizzled bf16 hi/lo image ----------------
__global__ void __launch_bounds__(256)
wsplit_kernel(const float* __restrict__ W) {
    const int step = gridDim.x * blockDim.x;
    const int TOT = 41 * 12288;                      // float4 count
    for (int v = blockIdx.x * blockDim.x + threadIdx.x; v < TOT; v += step) {
        const int s = v / 12288, rem = v % 12288;
        const int k = rem >> 5, q = rem & 31;        // k 0..383, q = float4-in-row
        const float4 w = *(const float4*)(W + (size_t)v * 4);
        const int c = k >> 6, kr = k & 63;
        float r0, r1, r2, r3;
        uint32_t h0 = hi2(w.x, w.y, r0, r1);
        uint32_t h1 = hi2(w.z, w.w, r2, r3);
        const size_t d = (size_t)s * WPRE_PER_S + (size_t)c * 32768
                       + (size_t)kr * 256
                       + ((((uint32_t)(q >> 1)) ^ ((uint32_t)kr & 7u)) << 4)
                       + (uint32_t)((q & 1) << 3);
        *(uint2*)(g_wpre + d)          = make_uint2(h0, h1);
        *(uint2*)(g_wpre + d + 16384u) = make_uint2(lo2(r0, r1), lo2(r2, r3));
    }
}

// ------------------------------ main kernel --------------------------------
__global__ void __launch_bounds__(NTHREADS, 1)
poslin_kernel(const float* __restrict__ x,
              const float* __restrict__ bias, float* __restrict__ out)
{
    extern __shared__ __align__(128) char smem[];
    const uint32_t sb = smem_u32(smem);
    const int tid  = threadIdx.x;
    const int lane = tid & 31;
    const int wid  = tid >> 5;                 // 0..19

    const int start = (int)(((long)blockIdx.x * NTILES) / GRIDSZ);
    const int end   = (int)(((long)(blockIdx.x + 1) * NTILES) / GRIDSZ);
    const int Ctot  = (end - start) * 6;

    if (wid >= 16) {
        // ====== PRODUCER (4 warps, 128 thr): x split + W via cp.async =======
        const int ptid = tid - 512;                  // 0..127
        const int xq = ptid & 15, xr0 = ptid >> 4;   // f4-in-row, row base 0..7
        const uint32_t xCvt = ((((uint32_t)(xq >> 1)) ^ ((uint32_t)xr0 & 7u)) << 4)
                            + (uint32_t)((xq & 1) << 3);

        int tL = start, cL = 0;

#define FILL(bufv) do {                                                         \
    const int s_ = tL >> 5, mt_ = tL & 31, bb_ = mt_ << 7;                      \
    const int e_ = (s_ - 1) * 128 + cL * 64 + xq * 4;                           \
    const bool v_ = (e_ >= 0) && (e_ < ROWSTRIDE);                              \
    const uint32_t bo_ = (uint32_t)(bufv) * BUFSTR;                             \
    /* W hi+lo 32KB, pre-swizzled -> raw 16B copies */                          \
    {                                                                           \
        const unsigned char* wsrc = g_wpre + (size_t)s_ * WPRE_PER_S            \
                                  + (size_t)cL * 32768 + (size_t)ptid * 16;     \
        const uint32_t wdst = sb + bo_ + O_WHI + (uint32_t)ptid * 16u;          \
        _Pragma("unroll")                                                       \
        for (int i = 0; i < 16; ++i)                                            \
            cp16(wdst + (uint32_t)(i * 2048), wsrc + (size_t)i * 2048);         \
        asm volatile("cp.async.commit_group;" ::: "memory");                    \
    }                                                                           \
    /* x: 16 float4 LDG (batched, MLP=16), then split+STS */                    \
    float4 xa[16];                                                              \
    _Pragma("unroll")                                                           \
    for (int it = 0; it < 16; ++it)                                             \
        xa[it] = v_ ? *(const float4*)(x + (size_t)(bb_ + xr0 + 8*it) * ROWSTRIDE + e_) \
                    : make_float4(0.f, 0.f, 0.f, 0.f);                          \
    _Pragma("unroll")                                                           \
    for (int it = 0; it < 16; ++it) {                                           \
        float r0_, r1_, r2_, r3_;                                               \
        uint32_t h0_ = hi2(xa[it].x, xa[it].y, r0_, r1_);                       \
        uint32_t h1_ = hi2(xa[it].z, xa[it].w, r2_, r3_);                       \
        uint32_t o_ = bo_ + (uint32_t)(xr0 + 8*it) * 128u + xCvt;               \
        *(uint2*)(smem + o_)         = make_uint2(h0_, h1_);                    \
        *(uint2*)(smem + o_ + O_XLO) = make_uint2(lo2(r0_, r1_), lo2(r2_, r3_));\
    }                                                                           \
    asm volatile("cp.async.wait_group 0;" ::: "memory");                        \
} while (0)

        FILL(0);
        if (++cL == 6) { cL = 0; ++tL; }
        for (int g = 0; g < Ctot; ++g) {
            __syncthreads();
            if (g + 1 < Ctot) {
                FILL((g + 1) & 1);
                if (++cL == 6) { cL = 0; ++tL; }
            }
        }
#undef FILL
    } else {
        // ================= CONSUMER (16 warps, 512 threads) =================
        const int m0 = (wid & 3) << 5;
        const int n0 = (wid >> 2) << 5;
        const int g8 = lane >> 2, tig = lane & 3;

        const uint32_t aRowB = (uint32_t)(m0 + (lane & 15));
        const uint32_t aKC   = (uint32_t)(lane >> 4);
        const uint32_t l7    = (uint32_t)(lane & 7);
        const uint32_t bKrB  = (uint32_t)(lane & 15);
        const uint32_t bNCB  = (uint32_t)((n0 >> 3) + (lane >> 4));

        int t = start, c = 0;
        float acc[2][4][4];

        for (int g = 0; g < Ctot; ++g) {
            __syncthreads();
            if (c == 0) {
                _Pragma("unroll")
                for (int i = 0; i < 2; ++i)
                    _Pragma("unroll")
                    for (int j = 0; j < 4; ++j)
                        _Pragma("unroll")
                        for (int u = 0; u < 4; ++u) acc[i][j][u] = 0.f;
            }
            {
                const uint32_t Ab = sb + (uint32_t)(g & 1) * BUFSTR;
                _Pragma("unroll")
                for (int ks = 0; ks < 4; ++ks) {
                    uint32_t ah[2][4], al[2][4];
                    _Pragma("unroll")
                    for (int i = 0; i < 2; ++i) {
                        uint32_t ad = Ab + (aRowB + 16u*i) * 128u
                                    + ((((uint32_t)(ks * 2) + aKC) ^ l7) << 4);
                        ldsm4(ah[i], ad);
                        ldsm4(al[i], ad + O_XLO);
                    }
                    _Pragma("unroll")
                    for (int jj = 0; jj < 2; ++jj) {
                        uint32_t bd = Ab + O_WHI + (bKrB + 16u*ks) * 256u
                                    + (((bNCB + 2u*jj) ^ l7) << 4);
                        uint32_t bh_[4], bl_[4];
                        ldsm4t(bh_, bd);
                        ldsm4t(bl_, bd + 16384u);
                        _Pragma("unroll")
                        for (int i = 0; i < 2; ++i) {
                            mma_bf16(acc[i][2*jj],     ah[i], bh_);
                            mma_bf16(acc[i][2*jj + 1], ah[i], bh_ + 2);
                            mma_bf16(acc[i][2*jj],     al[i], bh_);
                            mma_bf16(acc[i][2*jj + 1], al[i], bh_ + 2);
                        }
                        _Pragma("unroll")
                        for (int i = 0; i < 2; ++i) {
                            mma_bf16(acc[i][2*jj],     ah[i], bl_);
                            mma_bf16(acc[i][2*jj + 1], ah[i], bl_ + 2);
                        }
                    }
                }
            }
            if (c == 5) {
                const int s = t >> 5, bbase = (t & 31) << 7;
                const float* brow = bias + s * 128;
                _Pragma("unroll")
                for (int j = 0; j < 4; ++j) {
                    const int n = n0 + 8 * j + 2 * tig;
                    const float b0 = brow[n], b1 = brow[n + 1];
                    _Pragma("unroll")
                    for (int i = 0; i < 2; ++i) {
                        const size_t rb = (size_t)(bbase + m0 + 16 * i + g8) * ROWSTRIDE
                                        + (size_t)s * 128 + n;
                        float2 v0, v1;
                        v0.x = fmaxf(acc[i][j][0] + b0, 0.f);
                        v0.y = fmaxf(acc[i][j][1] + b1, 0.f);
                        v1.x = fmaxf(acc[i][j][2] + b0, 0.f);
                        v1.y = fmaxf(acc[i][j][3] + b1, 0.f);
                        *(float2*)(out + rb)                 = v0;
                        *(float2*)(out + rb + 8 * ROWSTRIDE) = v1;
                    }
                }
            }
            if (++c == 6) { c = 0; ++t; }
        }
    }
}

extern "C" void kernel_launch(void* const* d_in, const int* in_sizes, int n_in,
                              void* d_out, int out_size) {
    const float* x = (const float*)d_in[0];
    const float* W = (const float*)d_in[1];
    const float* b = (const float*)d_in[2];
    float* out = (float*)d_out;
    wsplit_kernel<<<296, 256>>>(W);
    cudaFuncSetAttribute(poslin_kernel,
                         cudaFuncAttributeMaxDynamicSharedMemorySize, SMEM_BYTES);
    poslin_kernel<<<GRIDSZ, NTHREADS, SMEM_BYTES>>>(x, b, out);
}

// round 13
// speedup vs baseline: 1.3096x; 1.2704x over previous
#include <cuda_runtime.h>
#include <cuda_bf16.h>
#include <cstdint>

#define ROWSTRIDE 5248
#define NTILES    1312
#define GRIDSZ    148
#define NTHREADS  512
#define SMEM_BYTES 131072

#define BUFSTR 65536u
#define O_XLO  16384u
#define O_WHI  32768u
// W lo at O_WHI + 16384

// Pre-split W image: per s: 6 chunks x 32768 B (hi 16KB + lo 16KB), pre-swizzled
#define WPRE_PER_S 196608
__device__ __align__(16) unsigned char g_wpre[41 * WPRE_PER_S];

static __device__ __forceinline__ uint32_t smem_u32(const void* p) {
    uint32_t a;
    asm("{ .reg .u64 t; cvta.to.shared.u64 t, %1; cvt.u32.u64 %0, t; }"
        : "=r"(a) : "l"(p));
    return a;
}
static __device__ __forceinline__ void ldsm4(uint32_t* r, uint32_t a) {
    asm volatile("ldmatrix.sync.aligned.m8n8.x4.shared.b16 {%0,%1,%2,%3}, [%4];"
                 : "=r"(r[0]), "=r"(r[1]), "=r"(r[2]), "=r"(r[3]) : "r"(a));
}
static __device__ __forceinline__ void ldsm4t(uint32_t* r, uint32_t a) {
    asm volatile("ldmatrix.sync.aligned.m8n8.x4.trans.shared.b16 {%0,%1,%2,%3}, [%4];"
                 : "=r"(r[0]), "=r"(r[1]), "=r"(r[2]), "=r"(r[3]) : "r"(a));
}
static __device__ __forceinline__ void mma_bf16(float* c, const uint32_t* a, const uint32_t* b) {
    asm volatile("mma.sync.aligned.m16n8k16.row.col.f32.bf16.bf16.f32 "
                 "{%0,%1,%2,%3}, {%4,%5,%6,%7}, {%8,%9}, {%0,%1,%2,%3};"
                 : "+f"(c[0]), "+f"(c[1]), "+f"(c[2]), "+f"(c[3])
                 : "r"(a[0]), "r"(a[1]), "r"(a[2]), "r"(a[3]), "r"(b[0]), "r"(b[1]));
}
static __device__ __forceinline__ uint32_t hi2(float a, float b, float& ra, float& rb) {
    __nv_bfloat16 ha = __float2bfloat16(a), hb = __float2bfloat16(b);
    ra = a - __bfloat162float(ha);
    rb = b - __bfloat162float(hb);
    return (uint32_t)__bfloat16_as_ushort(ha) | ((uint32_t)__bfloat16_as_ushort(hb) << 16);
}
static __device__ __forceinline__ uint32_t lo2(float a, float b) {
    return (uint32_t)__bfloat16_as_ushort(__float2bfloat16(a)) |
           ((uint32_t)__bfloat16_as_ushort(__float2bfloat16(b)) << 16);
}
static __device__ __forceinline__ void cp16(uint32_t dst, const void* src) {
    asm volatile("cp.async.cg.shared.global [%0], [%1], 16;"
                 :: "r"(dst), "l"(src) : "memory");
}

// ---------------- precompute: W -> swizzled bf16 hi/lo image ----------------
__global__ void __launch_bounds__(256)
wsplit_kernel(const float* __restrict__ W) {
    const int step = gridDim.x * blockDim.x;
    const int TOT = 41 * 12288;                      // float4 count
    for (int v = blockIdx.x * blockDim.x + threadIdx.x; v < TOT; v += step) {
        const int s = v / 12288, rem = v % 12288;
        const int k = rem >> 5, q = rem & 31;        // k 0..383, q = float4-in-row
        const float4 w = *(const float4*)(W + (size_t)v * 4);
        const int c = k >> 6, kr = k & 63;
        float r0, r1, r2, r3;
        uint32_t h0 = hi2(w.x, w.y, r0, r1);
        uint32_t h1 = hi2(w.z, w.w, r2, r3);
        const size_t d = (size_t)s * WPRE_PER_S + (size_t)c * 32768
                       + (size_t)kr * 256
                       + ((((uint32_t)(q >> 1)) ^ ((uint32_t)kr & 7u)) << 4)
                       + (uint32_t)((q & 1) << 3);
        *(uint2*)(g_wpre + d)          = make_uint2(h0, h1);
        *(uint2*)(g_wpre + d + 16384u) = make_uint2(lo2(r0, r1), lo2(r2, r3));
    }
}

// ------------------------------ main kernel --------------------------------
__global__ void __launch_bounds__(NTHREADS, 1)
poslin_kernel(const float* __restrict__ x,
              const float* __restrict__ bias, float* __restrict__ out)
{
    extern __shared__ __align__(128) char smem[];
    const uint32_t sb = smem_u32(smem);
    const int tid  = threadIdx.x;
    const int lane = tid & 31;
    const int wid  = tid >> 5;                 // 0..15

    const int start = (int)(((long)blockIdx.x * NTILES) / GRIDSZ);
    const int end   = (int)(((long)(blockIdx.x + 1) * NTILES) / GRIDSZ);
    const int Ctot  = (end - start) * 6;

    if (wid >= 8) {
        // ====== PRODUCER (8 warps, 256 thr): x split + W via cp.async =======
        const int ptid = tid - 256;                  // 0..255
        const int xq = ptid & 15, xr0 = ptid >> 4;   // f4-in-row, row base 0..15
        const uint32_t xCvt = ((((uint32_t)(xq >> 1)) ^ ((uint32_t)xr0 & 7u)) << 4)
                            + (uint32_t)((xq & 1) << 3);

        int tL = start, cL = 0;

#define FILL(bufv) do {                                                         \
    const int s_ = tL >> 5, mt_ = tL & 31, bb_ = mt_ << 7;                      \
    const int e_ = (s_ - 1) * 128 + cL * 64 + xq * 4;                           \
    const bool v_ = (e_ >= 0) && (e_ < ROWSTRIDE);                              \
    const uint32_t bo_ = (uint32_t)(bufv) * BUFSTR;                             \
    /* W hi+lo 32KB pre-swizzled: 8 x 16B per thread */                         \
    {                                                                           \
        const unsigned char* wsrc = g_wpre + (size_t)s_ * WPRE_PER_S            \
                                  + (size_t)cL * 32768 + (size_t)ptid * 16;     \
        const uint32_t wdst = sb + bo_ + O_WHI + (uint32_t)ptid * 16u;          \
        _Pragma("unroll")                                                       \
        for (int i = 0; i < 8; ++i)                                             \
            cp16(wdst + (uint32_t)(i * 4096), wsrc + (size_t)i * 4096);         \
        asm volatile("cp.async.commit_group;" ::: "memory");                    \
    }                                                                           \
    /* x: 8 float4 LDG (batched), split + STS */                                \
    float4 xa[8];                                                               \
    _Pragma("unroll")                                                           \
    for (int it = 0; it < 8; ++it)                                              \
        xa[it] = v_ ? *(const float4*)(x + (size_t)(bb_ + xr0 + 16*it) * ROWSTRIDE + e_) \
                    : make_float4(0.f, 0.f, 0.f, 0.f);                          \
    _Pragma("unroll")                                                           \
    for (int it = 0; it < 8; ++it) {                                            \
        float r0_, r1_, r2_, r3_;                                               \
        uint32_t h0_ = hi2(xa[it].x, xa[it].y, r0_, r1_);                       \
        uint32_t h1_ = hi2(xa[it].z, xa[it].w, r2_, r3_);                       \
        uint32_t o_ = bo_ + (uint32_t)(xr0 + 16*it) * 128u + xCvt;              \
        *(uint2*)(smem + o_)         = make_uint2(h0_, h1_);                    \
        *(uint2*)(smem + o_ + O_XLO) = make_uint2(lo2(r0_, r1_), lo2(r2_, r3_));\
    }                                                                           \
    asm volatile("cp.async.wait_group 0;" ::: "memory");                        \
} while (0)

        FILL(0);
        if (++cL == 6) { cL = 0; ++tL; }
        for (int g = 0; g < Ctot; ++g) {
            __syncthreads();
            if (g + 1 < Ctot) {
                FILL((g + 1) & 1);
                if (++cL == 6) { cL = 0; ++tL; }
            }
        }
#undef FILL
    } else {
        // ========== CONSUMER (8 warps, 256 threads): 64x32 warp tile ========
        const int m0 = (wid >> 2) << 6;        // 0, 64
        const int n0 = (wid & 3) << 5;         // 0, 32, 64, 96
        const int g8 = lane >> 2, tig = lane & 3;

        const uint32_t aRowB = (uint32_t)(m0 + (lane & 15));
        const uint32_t aKC   = (uint32_t)(lane >> 4);
        const uint32_t l7    = (uint32_t)(lane & 7);
        const uint32_t bKrB  = (uint32_t)(lane & 15);
        const uint32_t bNCB  = (uint32_t)((n0 >> 3) + (lane >> 4));

        int t = start, c = 0;
        float acc[4][4][4];                    // [i: m16 block][j: n8][4]

        for (int g = 0; g < Ctot; ++g) {
            __syncthreads();
            if (c == 0) {
                _Pragma("unroll")
                for (int i = 0; i < 4; ++i)
                    _Pragma("unroll")
                    for (int j = 0; j < 4; ++j)
                        _Pragma("unroll")
                        for (int u = 0; u < 4; ++u) acc[i][j][u] = 0.f;
            }
            {
                const uint32_t Ab = sb + (uint32_t)(g & 1) * BUFSTR;
                _Pragma("unroll")
                for (int ks = 0; ks < 4; ++ks) {
                    uint32_t ah[4][4], al[4][4];
                    _Pragma("unroll")
                    for (int i = 0; i < 4; ++i) {
                        uint32_t ad = Ab + (aRowB + 16u*i) * 128u
                                    + ((((uint32_t)(ks * 2) + aKC) ^ l7) << 4);
                        ldsm4(ah[i], ad);
                        ldsm4(al[i], ad + O_XLO);
                    }
                    _Pragma("unroll")
                    for (int jj = 0; jj < 2; ++jj) {
                        uint32_t bd = Ab + O_WHI + (bKrB + 16u*ks) * 256u
                                    + (((bNCB + 2u*jj) ^ l7) << 4);
                        uint32_t bh_[4], bl_[4];
                        ldsm4t(bh_, bd);
                        ldsm4t(bl_, bd + 16384u);
                        _Pragma("unroll")
                        for (int i = 0; i < 4; ++i) {
                            mma_bf16(acc[i][2*jj],     ah[i], bh_);
                            mma_bf16(acc[i][2*jj + 1], ah[i], bh_ + 2);
                            mma_bf16(acc[i][2*jj],     al[i], bh_);
                            mma_bf16(acc[i][2*jj + 1], al[i], bh_ + 2);
                        }
                        _Pragma("unroll")
                        for (int i = 0; i < 4; ++i) {
                            mma_bf16(acc[i][2*jj],     ah[i], bl_);
                            mma_bf16(acc[i][2*jj + 1], ah[i], bl_ + 2);
                        }
                    }
                }
            }
            if (c == 5) {
                const int s = t >> 5, bbase = (t & 31) << 7;
                const float* brow = bias + s * 128;
                _Pragma("unroll")
                for (int j = 0; j < 4; ++j) {
                    const int n = n0 + 8 * j + 2 * tig;
                    const float b0 = brow[n], b1 = brow[n + 1];
                    _Pragma("unroll")
                    for (int i = 0; i < 4; ++i) {
                        const size_t rb = (size_t)(bbase + m0 + 16 * i + g8) * ROWSTRIDE
                                        + (size_t)s * 128 + n;
                        float2 v0, v1;
                        v0.x = fmaxf(acc[i][j][0] + b0, 0.f);
                        v0.y = fmaxf(acc[i][j][1] + b1, 0.f);
                        v1.x = fmaxf(acc[i][j][2] + b0, 0.f);
                        v1.y = fmaxf(acc[i][j][3] + b1, 0.f);
                        *(float2*)(out + rb)                 = v0;
                        *(float2*)(out + rb + 8 * ROWSTRIDE) = v1;
                    }
                }
            }
            if (++c == 6) { c = 0; ++t; }
        }
    }
}

extern "C" void kernel_launch(void* const* d_in, const int* in_sizes, int n_in,
                              void* d_out, int out_size) {
    const float* x = (const float*)d_in[0];
    const float* W = (const float*)d_in[1];
    const float* b = (const float*)d_in[2];
    float* out = (float*)d_out;
    wsplit_kernel<<<296, 256>>>(W);
    cudaFuncSetAttribute(poslin_kernel,
                         cudaFuncAttributeMaxDynamicSharedMemorySize, SMEM_BYTES);
    poslin_kernel<<<GRIDSZ, NTHREADS, SMEM_BYTES>>>(x, b, out);
}

// round 14
// speedup vs baseline: 1.7061x; 1.3028x over previous
#include <cuda_runtime.h>
#include <cuda_fp16.h>
#include <cstdint>

#define ROWSTRIDE 5248
#define NTILES    1312
#define GRIDSZ    148
#define NTHREADS  512
#define SMEM_BYTES 98304

#define BUFSTR 49152u
#define O_XLO  16384u
#define O_WHI  32768u

// Pre-split W image: per s: 6 chunks x 16384 B (fp16, pre-swizzled)
#define WPRE_PER_S 98304
__device__ __align__(16) unsigned char g_wpre[41 * WPRE_PER_S];

static __device__ __forceinline__ uint32_t smem_u32(const void* p) {
    uint32_t a;
    asm("{ .reg .u64 t; cvta.to.shared.u64 t, %1; cvt.u32.u64 %0, t; }"
        : "=r"(a) : "l"(p));
    return a;
}
static __device__ __forceinline__ void ldsm4(uint32_t* r, uint32_t a) {
    asm volatile("ldmatrix.sync.aligned.m8n8.x4.shared.b16 {%0,%1,%2,%3}, [%4];"
                 : "=r"(r[0]), "=r"(r[1]), "=r"(r[2]), "=r"(r[3]) : "r"(a));
}
static __device__ __forceinline__ void ldsm4t(uint32_t* r, uint32_t a) {
    asm volatile("ldmatrix.sync.aligned.m8n8.x4.trans.shared.b16 {%0,%1,%2,%3}, [%4];"
                 : "=r"(r[0]), "=r"(r[1]), "=r"(r[2]), "=r"(r[3]) : "r"(a));
}
static __device__ __forceinline__ void mma_f16(float* c, const uint32_t* a, const uint32_t* b) {
    asm volatile("mma.sync.aligned.m16n8k16.row.col.f32.f16.f16.f32 "
                 "{%0,%1,%2,%3}, {%4,%5,%6,%7}, {%8,%9}, {%0,%1,%2,%3};"
                 : "+f"(c[0]), "+f"(c[1]), "+f"(c[2]), "+f"(c[3])
                 : "r"(a[0]), "r"(a[1]), "r"(a[2]), "r"(a[3]), "r"(b[0]), "r"(b[1]));
}
static __device__ __forceinline__ uint32_t hi2h(float a, float b, float& ra, float& rb) {
    __half ha = __float2half_rn(a), hb = __float2half_rn(b);
    ra = a - __half2float(ha);
    rb = b - __half2float(hb);
    return (uint32_t)__half_as_ushort(ha) | ((uint32_t)__half_as_ushort(hb) << 16);
}
static __device__ __forceinline__ uint32_t lo2h(float a, float b) {
    return (uint32_t)__half_as_ushort(__float2half_rn(a)) |
           ((uint32_t)__half_as_ushort(__float2half_rn(b)) << 16);
}
static __device__ __forceinline__ void cp16(uint32_t dst, const void* src) {
    asm volatile("cp.async.cg.shared.global [%0], [%1], 16;"
                 :: "r"(dst), "l"(src) : "memory");
}

// ------------- precompute: W fp32 -> swizzled fp16 image --------------------
__global__ void __launch_bounds__(256)
wsplit_kernel(const float* __restrict__ W) {
    const int step = gridDim.x * blockDim.x;
    const int TOT = 41 * 12288;                      // float4 count
    for (int v = blockIdx.x * blockDim.x + threadIdx.x; v < TOT; v += step) {
        const int s = v / 12288, rem = v % 12288;
        const int k = rem >> 5, q = rem & 31;        // k 0..383, q = float4-in-row
        const float4 w = *(const float4*)(W + (size_t)v * 4);
        const int c = k >> 6, kr = k & 63;
        const uint32_t h0 = lo2h(w.x, w.y);
        const uint32_t h1 = lo2h(w.z, w.w);
        const size_t d = (size_t)s * WPRE_PER_S + (size_t)c * 16384
                       + (size_t)kr * 256
                       + ((((uint32_t)(q >> 1)) ^ ((uint32_t)kr & 7u)) << 4)
                       + (uint32_t)((q & 1) << 3);
        *(uint2*)(g_wpre + d) = make_uint2(h0, h1);
    }
}

// ------------------------------ main kernel --------------------------------
__global__ void __launch_bounds__(NTHREADS, 1)
poslin_kernel(const float* __restrict__ x,
              const float* __restrict__ bias, float* __restrict__ out)
{
    extern __shared__ __align__(128) char smem[];
    const uint32_t sb = smem_u32(smem);
    const int tid  = threadIdx.x;
    const int lane = tid & 31;
    const int wid  = tid >> 5;                 // 0..15

    const int start = (int)(((long)blockIdx.x * NTILES) / GRIDSZ);
    const int end   = (int)(((long)(blockIdx.x + 1) * NTILES) / GRIDSZ);
    const int Ctot  = (end - start) * 6;

    if (wid >= 8) {
        // ====== PRODUCER (8 warps, 256 thr): x fp16-split + W cp.async ======
        const int ptid = tid - 256;                  // 0..255
        const int xq = ptid & 15, xr0 = ptid >> 4;   // f4-in-row, row base 0..15
        const uint32_t xCvt = ((((uint32_t)(xq >> 1)) ^ ((uint32_t)xr0 & 7u)) << 4)
                            + (uint32_t)((xq & 1) << 3);

        int tL = start, cL = 0;

#define FILL(bufv) do {                                                         \
    const int s_ = tL >> 5, mt_ = tL & 31, bb_ = mt_ << 7;                      \
    const int e_ = (s_ - 1) * 128 + cL * 64 + xq * 4;                           \
    const bool v_ = (e_ >= 0) && (e_ < ROWSTRIDE);                              \
    const uint32_t bo_ = (uint32_t)(bufv) * BUFSTR;                             \
    /* W fp16 16KB pre-swizzled: 4 x 16B per thread */                          \
    {                                                                           \
        const unsigned char* wsrc = g_wpre + (size_t)s_ * WPRE_PER_S            \
                                  + (size_t)cL * 16384 + (size_t)ptid * 16;     \
        const uint32_t wdst = sb + bo_ + O_WHI + (uint32_t)ptid * 16u;          \
        _Pragma("unroll")                                                       \
        for (int i = 0; i < 4; ++i)                                             \
            cp16(wdst + (uint32_t)(i * 4096), wsrc + (size_t)i * 4096);         \
        asm volatile("cp.async.commit_group;" ::: "memory");                    \
    }                                                                           \
    float4 xa[8];                                                               \
    _Pragma("unroll")                                                           \
    for (int it = 0; it < 8; ++it)                                              \
        xa[it] = v_ ? *(const float4*)(x + (size_t)(bb_ + xr0 + 16*it) * ROWSTRIDE + e_) \
                    : make_float4(0.f, 0.f, 0.f, 0.f);                          \
    _Pragma("unroll")                                                           \
    for (int it = 0; it < 8; ++it) {                                            \
        float r0_, r1_, r2_, r3_;                                               \
        uint32_t h0_ = hi2h(xa[it].x, xa[it].y, r0_, r1_);                      \
        uint32_t h1_ = hi2h(xa[it].z, xa[it].w, r2_, r3_);                      \
        uint32_t o_ = bo_ + (uint32_t)(xr0 + 16*it) * 128u + xCvt;              \
        *(uint2*)(smem + o_)         = make_uint2(h0_, h1_);                    \
        *(uint2*)(smem + o_ + O_XLO) = make_uint2(lo2h(r0_, r1_), lo2h(r2_, r3_)); \
    }                                                                           \
    asm volatile("cp.async.wait_group 0;" ::: "memory");                        \
} while (0)

        FILL(0);
        if (++cL == 6) { cL = 0; ++tL; }
        for (int g = 0; g < Ctot; ++g) {
            __syncthreads();
            if (g + 1 < Ctot) {
                FILL((g + 1) & 1);
                if (++cL == 6) { cL = 0; ++tL; }
            }
        }
#undef FILL
    } else {
        // ========== CONSUMER (8 warps, 256 threads): 64x32 warp tile ========
        const int m0 = (wid >> 2) << 6;        // 0, 64
        const int n0 = (wid & 3) << 5;         // 0, 32, 64, 96
        const int g8 = lane >> 2, tig = lane & 3;
        const int ksoff = (wid & 1) << 1;      // de-correlate SMSP warp pairs

        const uint32_t aRowB = (uint32_t)(m0 + (lane & 15));
        const uint32_t aKC   = (uint32_t)(lane >> 4);
        const uint32_t l7    = (uint32_t)(lane & 7);
        const uint32_t bKrB  = (uint32_t)(lane & 15);
        const uint32_t bNCB  = (uint32_t)((n0 >> 3) + (lane >> 4));

        int t = start, c = 0;
        float acc[4][4][4];                    // [i: m16 block][j: n8][4]

        for (int g = 0; g < Ctot; ++g) {
            __syncthreads();
            if (c == 0) {
                _Pragma("unroll")
                for (int i = 0; i < 4; ++i)
                    _Pragma("unroll")
                    for (int j = 0; j < 4; ++j)
                        _Pragma("unroll")
                        for (int u = 0; u < 4; ++u) acc[i][j][u] = 0.f;
            }
            {
                const uint32_t Ab = sb + (uint32_t)(g & 1) * BUFSTR;
                _Pragma("unroll")
                for (int ks2 = 0; ks2 < 4; ++ks2) {
                    const int ks = (ks2 + ksoff) & 3;
                    uint32_t ah[4][4], al[4][4];
                    _Pragma("unroll")
                    for (int i = 0; i < 4; ++i) {
                        uint32_t ad = Ab + (aRowB + 16u*i) * 128u
                                    + ((((uint32_t)(ks * 2) + aKC) ^ l7) << 4);
                        ldsm4(ah[i], ad);
                        ldsm4(al[i], ad + O_XLO);
                    }
                    _Pragma("unroll")
                    for (int jj = 0; jj < 2; ++jj) {
                        uint32_t bd = Ab + O_WHI + (bKrB + 16u*ks) * 256u
                                    + (((bNCB + 2u*jj) ^ l7) << 4);
                        uint32_t bh_[4];
                        ldsm4t(bh_, bd);
                        _Pragma("unroll")
                        for (int i = 0; i < 4; ++i) {
                            mma_f16(acc[i][2*jj],     ah[i], bh_);
                            mma_f16(acc[i][2*jj + 1], ah[i], bh_ + 2);
                            mma_f16(acc[i][2*jj],     al[i], bh_);
                            mma_f16(acc[i][2*jj + 1], al[i], bh_ + 2);
                        }
                    }
                }
            }
            if (c == 5) {
                const int s = t >> 5, bbase = (t & 31) << 7;
                const float* brow = bias + s * 128;
                _Pragma("unroll")
                for (int j = 0; j < 4; ++j) {
                    const int n = n0 + 8 * j + 2 * tig;
                    const float b0 = brow[n], b1 = brow[n + 1];
                    _Pragma("unroll")
                    for (int i = 0; i < 4; ++i) {
                        const size_t rb = (size_t)(bbase + m0 + 16 * i + g8) * ROWSTRIDE
                                        + (size_t)s * 128 + n;
                        float2 v0, v1;
                        v0.x = fmaxf(acc[i][j][0] + b0, 0.f);
                        v0.y = fmaxf(acc[i][j][1] + b1, 0.f);
                        v1.x = fmaxf(acc[i][j][2] + b0, 0.f);
                        v1.y = fmaxf(acc[i][j][3] + b1, 0.f);
                        *(float2*)(out + rb)                 = v0;
                        *(float2*)(out + rb + 8 * ROWSTRIDE) = v1;
                    }
                }
            }
            if (++c == 6) { c = 0; ++t; }
        }
    }
}

extern "C" void kernel_launch(void* const* d_in, const int* in_sizes, int n_in,
                              void* d_out, int out_size) {
    const float* x = (const float*)d_in[0];
    const float* W = (const float*)d_in[1];
    const float* b = (const float*)d_in[2];
    float* out = (float*)d_out;
    wsplit_kernel<<<296, 256>>>(W);
    cudaFuncSetAttribute(poslin_kernel,
                         cudaFuncAttributeMaxDynamicSharedMemorySize, SMEM_BYTES);
    poslin_kernel<<<GRIDSZ, NTHREADS, SMEM_BYTES>>>(x, b, out);
}

// round 15
// speedup vs baseline: 2.4121x; 1.4137x over previous
#include <cuda_runtime.h>
#include <cuda_fp16.h>
#include <cstdint>

#define ROWSTRIDE 5248
#define NTILES    1312
#define GRIDSZ    148
#define NTHREADS  512
#define SMEM_BYTES 131072

#define BUFSTR 65536u
#define O_W    32768u

// Pre-converted W image: per s: 3 chunks x 32768 B (fp16, pre-swizzled)
#define WPRE_PER_S 98304
__device__ __align__(16) unsigned char g_wpre[41 * WPRE_PER_S];

static __device__ __forceinline__ uint32_t smem_u32(const void* p) {
    uint32_t a;
    asm("{ .reg .u64 t; cvta.to.shared.u64 t, %1; cvt.u32.u64 %0, t; }"
        : "=r"(a) : "l"(p));
    return a;
}
static __device__ __forceinline__ void ldsm4(uint32_t* r, uint32_t a) {
    asm volatile("ldmatrix.sync.aligned.m8n8.x4.shared.b16 {%0,%1,%2,%3}, [%4];"
                 : "=r"(r[0]), "=r"(r[1]), "=r"(r[2]), "=r"(r[3]) : "r"(a));
}
static __device__ __forceinline__ void ldsm4t(uint32_t* r, uint32_t a) {
    asm volatile("ldmatrix.sync.aligned.m8n8.x4.trans.shared.b16 {%0,%1,%2,%3}, [%4];"
                 : "=r"(r[0]), "=r"(r[1]), "=r"(r[2]), "=r"(r[3]) : "r"(a));
}
static __device__ __forceinline__ void mma_f16(float* c, const uint32_t* a, const uint32_t* b) {
    asm volatile("mma.sync.aligned.m16n8k16.row.col.f32.f16.f16.f32 "
                 "{%0,%1,%2,%3}, {%4,%5,%6,%7}, {%8,%9}, {%0,%1,%2,%3};"
                 : "+f"(c[0]), "+f"(c[1]), "+f"(c[2]), "+f"(c[3])
                 : "r"(a[0]), "r"(a[1]), "r"(a[2]), "r"(a[3]), "r"(b[0]), "r"(b[1]));
}
static __device__ __forceinline__ uint32_t cvt2h(float a, float b) {
    return (uint32_t)__half_as_ushort(__float2half_rn(a)) |
           ((uint32_t)__half_as_ushort(__float2half_rn(b)) << 16);
}
static __device__ __forceinline__ void cp16(uint32_t dst, const void* src) {
    asm volatile("cp.async.cg.shared.global [%0], [%1], 16;"
                 :: "r"(dst), "l"(src) : "memory");
}

// ------------- precompute: W fp32 -> swizzled fp16 image --------------------
__global__ void __launch_bounds__(256)
wsplit_kernel(const float* __restrict__ W) {
    const int step = gridDim.x * blockDim.x;
    const int TOT = 41 * 12288;                      // float4 count
    for (int v = blockIdx.x * blockDim.x + threadIdx.x; v < TOT; v += step) {
        const int s = v / 12288, rem = v % 12288;
        const int k = rem >> 5, q = rem & 31;        // k 0..383, q = float4-in-row
        const float4 w = *(const float4*)(W + (size_t)v * 4);
        const int c = k >> 7, kr = k & 127;          // 3 chunks of 128 k-rows
        const size_t d = (size_t)s * WPRE_PER_S + (size_t)c * 32768
                       + (size_t)kr * 256
                       + ((((uint32_t)(q >> 1)) ^ ((uint32_t)kr & 7u)) << 4)
                       + (uint32_t)((q & 1) << 3);
        *(uint2*)(g_wpre + d) = make_uint2(cvt2h(w.x, w.y), cvt2h(w.z, w.w));
    }
}

// ------------------------------ main kernel --------------------------------
__global__ void __launch_bounds__(NTHREADS, 1)
poslin_kernel(const float* __restrict__ x,
              const float* __restrict__ bias, float* __restrict__ out)
{
    extern __shared__ __align__(128) char smem[];
    const uint32_t sb = smem_u32(smem);
    const int tid  = threadIdx.x;
    const int lane = tid & 31;
    const int wid  = tid >> 5;                 // 0..15

    const int start = (int)(((long)blockIdx.x * NTILES) / GRIDSZ);
    const int end   = (int)(((long)(blockIdx.x + 1) * NTILES) / GRIDSZ);
    const int Ctot  = (end - start) * 3;       // 3 K128-chunks per tile

    if (wid >= 8) {
        // ====== PRODUCER (8 warps, 256 thr): x fp16 + W cp.async ============
        const int ptid = tid - 256;                  // 0..255
        const int xq = ptid & 31, xr0 = ptid >> 5;   // f4-in-row (0..31), row base 0..7
        const uint32_t xCvt = ((((uint32_t)(xq >> 1)) ^ ((uint32_t)xr0 & 7u)) << 4)
                            + (uint32_t)((xq & 1) << 3);

        int tL = start, cL = 0;

#define FILL(bufv) do {                                                         \
    const int s_ = tL >> 5, mt_ = tL & 31, bb_ = mt_ << 7;                      \
    const int e_ = (s_ - 1 + cL) * 128 + xq * 4;                                \
    const bool v_ = (e_ >= 0) && (e_ < ROWSTRIDE);                              \
    const uint32_t bo_ = (uint32_t)(bufv) * BUFSTR;                             \
    /* W fp16 32KB pre-swizzled: 8 x 16B per thread */                          \
    {                                                                           \
        const unsigned char* wsrc = g_wpre + (size_t)s_ * WPRE_PER_S            \
                                  + (size_t)cL * 32768 + (size_t)ptid * 16;     \
        const uint32_t wdst = sb + bo_ + O_W + (uint32_t)ptid * 16u;            \
        _Pragma("unroll")                                                       \
        for (int i = 0; i < 8; ++i)                                             \
            cp16(wdst + (uint32_t)(i * 4096), wsrc + (size_t)i * 4096);         \
        asm volatile("cp.async.commit_group;" ::: "memory");                    \
    }                                                                           \
    /* x: 16 float4 LDG (batched), fp16 cvt + STS */                            \
    float4 xa[16];                                                              \
    _Pragma("unroll")                                                           \
    for (int it = 0; it < 16; ++it)                                             \
        xa[it] = v_ ? *(const float4*)(x + (size_t)(bb_ + xr0 + 8*it) * ROWSTRIDE + e_) \
                    : make_float4(0.f, 0.f, 0.f, 0.f);                          \
    _Pragma("unroll")                                                           \
    for (int it = 0; it < 16; ++it) {                                           \
        uint32_t o_ = bo_ + (uint32_t)(xr0 + 8*it) * 256u + xCvt;               \
        *(uint2*)(smem + o_) = make_uint2(cvt2h(xa[it].x, xa[it].y),            \
                                          cvt2h(xa[it].z, xa[it].w));           \
    }                                                                           \
    asm volatile("cp.async.wait_group 0;" ::: "memory");                        \
} while (0)

        FILL(0);
        if (++cL == 3) { cL = 0; ++tL; }
        for (int g = 0; g < Ctot; ++g) {
            __syncthreads();
            if (g + 1 < Ctot) {
                FILL((g + 1) & 1);
                if (++cL == 3) { cL = 0; ++tL; }
            }
        }
#undef FILL
    } else {
        // ========== CONSUMER (8 warps, 256 threads): 64x32 warp tile ========
        const int m0 = (wid >> 2) << 6;        // 0, 64
        const int n0 = (wid & 3) << 5;         // 0, 32, 64, 96
        const int g8 = lane >> 2, tig = lane & 3;
        const int ksoff = (wid & 1) << 2;      // de-correlate SMSP warp pairs

        const uint32_t aRowB = (uint32_t)(m0 + (lane & 15));
        const uint32_t aKC   = (uint32_t)(lane >> 4);
        const uint32_t l7    = (uint32_t)(lane & 7);
        const uint32_t bKrB  = (uint32_t)(lane & 15);
        const uint32_t bNCB  = (uint32_t)((n0 >> 3) + (lane >> 4));

        int t = start, c = 0;
        float acc[4][4][4];                    // [i: m16 block][j: n8][4]

        for (int g = 0; g < Ctot; ++g) {
            __syncthreads();
            if (c == 0) {
                _Pragma("unroll")
                for (int i = 0; i < 4; ++i)
                    _Pragma("unroll")
                    for (int j = 0; j < 4; ++j)
                        _Pragma("unroll")
                        for (int u = 0; u < 4; ++u) acc[i][j][u] = 0.f;
            }
            {
                const uint32_t Ab = sb + (uint32_t)(g & 1) * BUFSTR;
                _Pragma("unroll")
                for (int ks2 = 0; ks2 < 8; ++ks2) {
                    const int ks = (ks2 + ksoff) & 7;
                    uint32_t ah[4][4];
                    _Pragma("unroll")
                    for (int i = 0; i < 4; ++i) {
                        uint32_t ad = Ab + (aRowB + 16u*i) * 256u
                                    + ((((uint32_t)(ks * 2) + aKC) ^ l7) << 4);
                        ldsm4(ah[i], ad);
                    }
                    _Pragma("unroll")
                    for (int jj = 0; jj < 2; ++jj) {
                        uint32_t bd = Ab + O_W + (bKrB + 16u*ks) * 256u
                                    + (((bNCB + 2u*jj) ^ l7) << 4);
                        uint32_t bh_[4];
                        ldsm4t(bh_, bd);
                        _Pragma("unroll")
                        for (int i = 0; i < 4; ++i) {
                            mma_f16(acc[i][2*jj],     ah[i], bh_);
                            mma_f16(acc[i][2*jj + 1], ah[i], bh_ + 2);
                        }
                    }
                }
            }
            if (c == 2) {
                const int s = t >> 5, bbase = (t & 31) << 7;
                const float* brow = bias + s * 128;
                _Pragma("unroll")
                for (int j = 0; j < 4; ++j) {
                    const int n = n0 + 8 * j + 2 * tig;
                    const float b0 = brow[n], b1 = brow[n + 1];
                    _Pragma("unroll")
                    for (int i = 0; i < 4; ++i) {
                        const size_t rb = (size_t)(bbase + m0 + 16 * i + g8) * ROWSTRIDE
                                        + (size_t)s * 128 + n;
                        float2 v0, v1;
                        v0.x = fmaxf(acc[i][j][0] + b0, 0.f);
                        v0.y = fmaxf(acc[i][j][1] + b1, 0.f);
                        v1.x = fmaxf(acc[i][j][2] + b0, 0.f);
                        v1.y = fmaxf(acc[i][j][3] + b1, 0.f);
                        *(float2*)(out + rb)                 = v0;
                        *(float2*)(out + rb + 8 * ROWSTRIDE) = v1;
                    }
                }
            }
            if (++c == 3) { c = 0; ++t; }
        }
    }
}

extern "C" void kernel_launch(void* const* d_in, const int* in_sizes, int n_in,
                              void* d_out, int out_size) {
    const float* x = (const float*)d_in[0];
    const float* W = (const float*)d_in[1];
    const float* b = (const float*)d_in[2];
    float* out = (float*)d_out;
    wsplit_kernel<<<296, 256>>>(W);
    cudaFuncSetAttribute(poslin_kernel,
                         cudaFuncAttributeMaxDynamicSharedMemorySize, SMEM_BYTES);
    poslin_kernel<<<GRIDSZ, NTHREADS, SMEM_BYTES>>>(x, b, out);
}